// round 8
// baseline (speedup 1.0000x reference)
#include <cuda_runtime.h>
#include <cuda_bf16.h>
#include <math.h>

#define BS 16
#define HDIM 2048
#define QL 768
#define KVL 512
#define DR 64
#define DN 128
#define NH 16
#define NIH 8
#define IDXD 128
#define BLKSZ 128
#define BPS 32
#define MAXKV 4096
#define TOPK 1024
#define NSPLIT 16
#define SPLITROWS 64

#define NZ1 32          /* stage1 K-slices of 64 */
#define NZ2 12          /* stage2 K-slices of 64 */
#define T1DIM 1472
#define T2DIM 4104

#define ATT_SCALE 0.07216878364870323f
#define IDX_SCALE 0.08838834764831845f

#define NBMAX 448
#define SMSZ 42240

/* unit id layout (all deps point to strictly smaller ids -> deadlock-free) */
#define U_P0    0          /* 384: stage1 partials  (cx,bg,z) */
#define U_P1    384        /* 16 : norms (b)                  */
#define U_P2    400        /* 408: stage2 partials (cx,bg,z)  */
#define U_P2B   808        /* 16 : stage2 reduce (b)          */
#define U_QP    824        /* 64 : qprep (h,cc,bg)            */
#define U_ISC   888        /* 512: iscore (b,chunk) b-major   */
#define U_TOPK  1400       /* 16 : topk (b)                   */
#define U_ATTN  1416       /* 256: attn (b,s) b-major         */
#define U_COMB  1672       /* 256: combine (b,h) b-major      */
#define U_TOTAL 1928

/* counter indices in g_cnt */
#define C_P0   0    /* +bg, target 192 */
#define C_P1   2    /* +bg, target 8   */
#define C_P2   4    /* +bg, target 204 */
#define C_P2B  6    /* +bg, target 8   */
#define C_QP   8    /* +bg, target 32  */
#define C_ISC  16   /* +b,  target 32  */
#define C_TOPK 32   /* +b,  target 1   */
#define C_ATTN 48   /* +b,  target 16  */

// ---------------- scratch ----------------
__device__ float g_t1p[NZ1][BS][T1DIM];
__device__ float g_t2p[NZ2][BS][T2DIM];
__device__ float g_cq[BS][QL];
__device__ float g_ckv[BS][KVL];
__device__ float g_kr[BS][DR];
__device__ float g_ki[BS][IDXD];
__device__ float g_q[BS][NH * 192];
__device__ float g_qi[BS][NIH * IDXD];
__device__ float g_hw[BS][NIH];
__device__ float g_qpe[BS][NH][DR];
__device__ float g_qlat[BS][NH][KVL];
__device__ float g_isc[BS][MAXKV];
__device__ int   g_sel[BS][TOPK];
__device__ float g_selval[BS][TOPK];
__device__ float g_m[BS][NSPLIT][NH];
__device__ float g_l[BS][NSPLIT][NH];
__device__ float g_op[BS][NSPLIT][NH][KVL];

__device__ unsigned g_cnt[64];
__device__ unsigned g_ack;

__device__ __forceinline__ void waitc(int idx, unsigned target) {
    if (threadIdx.x == 0) {
        volatile unsigned* c = &g_cnt[idx];
        while (*c < target) __nanosleep(64);
        __threadfence();
    }
    __syncthreads();
}
__device__ __forceinline__ void waitc2(int i1, unsigned t1, int i2, unsigned t2) {
    if (threadIdx.x == 0) {
        volatile unsigned* c1 = &g_cnt[i1];
        volatile unsigned* c2 = &g_cnt[i2];
        while (*c1 < t1) __nanosleep(64);
        while (*c2 < t2) __nanosleep(64);
        __threadfence();
    }
    __syncthreads();
}
__device__ __forceinline__ void donec(int idx) {
    __syncthreads();
    if (threadIdx.x == 0) { __threadfence(); atomicAdd(&g_cnt[idx], 1u); }
}

__device__ __forceinline__ float blockSum256(float v, float* buf) {
    int tid = threadIdx.x;
    buf[tid] = v;
    __syncthreads();
    for (int s = 128; s > 0; s >>= 1) {
        if (tid < s) buf[tid] += buf[tid + s];
        __syncthreads();
    }
    float r = buf[0];
    __syncthreads();
    return r;
}

__global__ void __launch_bounds__(256, 3)
k_mega(const float* __restrict__ x, const float* __restrict__ w_dq,
       const float* __restrict__ w_uq_qr, const float* __restrict__ w_uk,
       const float* __restrict__ w_dkv, const float* __restrict__ gamma_cq,
       const float* __restrict__ gamma_ckv, const float* __restrict__ sinp,
       const float* __restrict__ cosp, const int* __restrict__ cidx,
       const float* __restrict__ kvc, const float* __restrict__ krc,
       const int* __restrict__ bt, const int* __restrict__ act_seqs,
       const float* __restrict__ w_idx_qb, const float* __restrict__ w_idxk,
       const float* __restrict__ w_idx_proj, const float* __restrict__ in_g,
       const float* __restrict__ in_b, const float* __restrict__ ikc,
       float* __restrict__ out, int nb)
{
    __shared__ __align__(16) char sm_raw[SMSZ];
    int tid = threadIdx.x;
    int bx = blockIdx.x;

    for (int u = bx; u < U_TOTAL; u += nb) {
        if (u < U_P1) {
            // ===== P0: stage1 partials, 8 batches/unit, 64-deep K slices =====
            int cx = u % 6, bg = (u / 6) & 1, z = u / 12;
            int i0 = z * 64, b0 = bg * 8;
            float* s_x = (float*)sm_raw;
            for (int idx = tid; idx < 8 * 64; idx += 256) {
                int bb = idx >> 6, ii = idx & 63;
                s_x[idx] = x[(b0 + bb) * HDIM + i0 + ii];
            }
            __syncthreads();
            int col = cx * 256 + tid;
            if (col < T1DIM) {
                const float* W; int stride, c;
                if (col < QL)                 { W = w_dq;   stride = QL;       c = col; }
                else if (col < QL + KVL + DR) { W = w_dkv;  stride = KVL + DR; c = col - QL; }
                else                          { W = w_idxk; stride = IDXD;     c = col - (QL + KVL + DR); }
                const float* wp = W + (size_t)i0 * stride + c;
                float acc[8];
                #pragma unroll
                for (int b = 0; b < 8; b++) acc[b] = 0.f;
                #pragma unroll 8
                for (int i = 0; i < 64; i++) {
                    float w = wp[(size_t)i * stride];
                    #pragma unroll
                    for (int b = 0; b < 8; b++) acc[b] += s_x[b * 64 + i] * w;
                }
                #pragma unroll
                for (int b = 0; b < 8; b++) g_t1p[z][b0 + b][col] = acc[b];
            }
            donec(C_P0 + bg);
        } else if (u < U_P2) {
            // ===== P1: norms + rope(kr) =====
            int b = u - U_P1;
            waitc(C_P0 + (b >> 3), 192);
            float* s_t  = (float*)sm_raw;
            float* sred = (float*)(sm_raw + T1DIM * 4 + 64);
            for (int i = tid; i < T1DIM; i += 256) {
                float a = 0.f;
                #pragma unroll
                for (int z = 0; z < NZ1; z++) a += g_t1p[z][b][i];
                s_t[i] = a;
            }
            __syncthreads();
            float ss = 0.f;
            for (int i = tid; i < QL; i += 256) ss += s_t[i] * s_t[i];
            ss = blockSum256(ss, sred);
            float r = rsqrtf(ss / (float)QL + 1e-6f);
            for (int i = tid; i < QL; i += 256) g_cq[b][i] = s_t[i] * r * gamma_cq[i];
            float s2 = 0.f;
            for (int i = tid; i < KVL; i += 256) { float v = s_t[QL + i]; s2 += v * v; }
            s2 = blockSum256(s2, sred);
            float r2 = rsqrtf(s2 / (float)KVL + 1e-6f);
            for (int i = tid; i < KVL; i += 256) g_ckv[b][i] = s_t[QL + i] * r2 * gamma_ckv[i];
            if (tid < DR) {
                int d = tid;
                float v = s_t[QL + KVL + d];
                float rot = (d < 32) ? -s_t[QL + KVL + d + 32] : s_t[QL + KVL + d - 32];
                g_kr[b][d] = v * cosp[b * DR + d] + rot * sinp[b * DR + d];
            }
            float sm = 0.f;
            for (int i = tid; i < IDXD; i += 256) sm += s_t[QL + KVL + DR + i];
            sm = blockSum256(sm, sred);
            float mean = sm / (float)IDXD;
            float sv = 0.f;
            for (int i = tid; i < IDXD; i += 256) { float c = s_t[QL + KVL + DR + i] - mean; sv += c * c; }
            sv = blockSum256(sv, sred);
            float rv = rsqrtf(sv / (float)IDXD + 1e-6f);
            for (int i = tid; i < IDXD; i += 256) {
                float c = s_t[QL + KVL + DR + i] - mean;
                g_ki[b][i] = c * rv * in_g[i] + in_b[i];
            }
            donec(C_P1 + (b >> 3));
        } else if (u < U_P2B) {
            // ===== P2: stage2 partials, 8 batches/unit =====
            int idx0 = u - U_P2;
            int cx = idx0 % 17, bg = (idx0 / 17) & 1, z = idx0 / 34;
            waitc(C_P1 + bg, 8);
            int i0 = z * 64, b0 = bg * 8;
            float* s_cq = (float*)sm_raw;
            for (int idx = tid; idx < 8 * 64; idx += 256) {
                int bb = idx >> 6, ii = idx & 63;
                s_cq[idx] = g_cq[b0 + bb][i0 + ii];
            }
            __syncthreads();
            int col = cx * 256 + tid;
            if (col < T2DIM) {
                const float* W; int stride, c;
                if (col < 3072)      { W = w_uq_qr;    stride = 3072; c = col; }
                else if (col < 4096) { W = w_idx_qb;   stride = 1024; c = col - 3072; }
                else                 { W = w_idx_proj; stride = 8;    c = col - 4096; }
                const float* wp = W + (size_t)i0 * stride + c;
                float acc[8];
                #pragma unroll
                for (int b = 0; b < 8; b++) acc[b] = 0.f;
                #pragma unroll 8
                for (int i = 0; i < 64; i++) {
                    float w = wp[(size_t)i * stride];
                    #pragma unroll
                    for (int b = 0; b < 8; b++) acc[b] += s_cq[b * 64 + i] * w;
                }
                #pragma unroll
                for (int b = 0; b < 8; b++) g_t2p[z][b0 + b][col] = acc[b];
            }
            donec(C_P2 + bg);
        } else if (u < U_QP) {
            // ===== P2b: reduce stage2 partials for one batch =====
            int b = u - U_P2B;
            waitc(C_P2 + (b >> 3), 204);
            for (int col = tid; col < T2DIM; col += 256) {
                float a = 0.f;
                #pragma unroll
                for (int z = 0; z < NZ2; z++) a += g_t2p[z][b][col];
                if (col < 3072)      g_q[b][col] = a;
                else if (col < 4096) g_qi[b][col - 3072] = a;
                else                 g_hw[b][col - 4096] = a;
            }
            donec(C_P2B + (b >> 3));
        } else if (u < U_ISC) {
            // ===== qprep: 8 batches/unit =====
            int idx0 = u - U_QP;
            int h = idx0 & 15, r = idx0 >> 4;
            int cc = r & 1, bg = r >> 1;
            waitc(C_P2B + bg, 8);
            int b0 = bg * 8;
            float* s_qn = (float*)sm_raw;
            for (int idx = tid; idx < 1024; idx += 256) {
                int bb = idx >> 7, d = idx & 127;
                s_qn[idx] = g_q[b0 + bb][h * 192 + d];
            }
            if (cc == 0) {
                for (int idx = tid; idx < 512; idx += 256) {
                    int bb = idx >> 6, d = idx & 63;
                    int b = b0 + bb;
                    float v = g_q[b][h * 192 + DN + d];
                    float rot = (d < 32) ? -g_q[b][h * 192 + DN + d + 32] : g_q[b][h * 192 + DN + d - 32];
                    g_qpe[b][h][d] = v * cosp[b * DR + d] + rot * sinp[b * DR + d];
                }
            }
            __syncthreads();
            int c = cc * 256 + tid;
            const float* wk = w_uk + (size_t)h * DN * KVL + c;
            float acc[8];
            #pragma unroll
            for (int b = 0; b < 8; b++) acc[b] = 0.f;
            #pragma unroll 8
            for (int d = 0; d < DN; d++) {
                float w = wk[(size_t)d * KVL];
                #pragma unroll
                for (int b = 0; b < 8; b++) acc[b] += s_qn[b * 128 + d] * w;
            }
            #pragma unroll
            for (int b = 0; b < 8; b++) g_qlat[b0 + b][h][c] = acc[b];
            donec(C_QP + bg);
        } else if (u < U_TOPK) {
            // ===== iscore =====
            int idx0 = u - U_ISC;
            int b = idx0 >> 5, chunk = idx0 & 31;
            waitc(C_P2B + (b >> 3), 8);
            float* s_qi = (float*)sm_raw;
            float* s_hw = (float*)(sm_raw + 4096);
            for (int i = tid; i < NIH * IDXD; i += 256) s_qi[i] = g_qi[b][i];
            if (tid < NIH) s_hw[tid] = g_hw[b][tid];
            __syncthreads();
            int warp = tid >> 5, lane = tid & 31;
            int act = act_seqs[b];
            int ci = cidx[b];
            for (int r = warp; r < 128; r += 8) {
                int n = chunk * 128 + r;
                if (n >= act) { if (lane == 0) g_isc[b][n] = -1e9f; continue; }
                int blk = bt[b * BPS + (n >> 7)];
                long flat = (long)blk * BLKSZ + (n & 127);
                const float* kr = (flat == (long)ci) ? g_ki[b] : ikc + flat * IDXD;
                float4 kv = *(const float4*)(kr + lane * 4);
                float acc[NIH];
                #pragma unroll
                for (int h = 0; h < NIH; h++) {
                    float4 q = *(const float4*)&s_qi[h * IDXD + lane * 4];
                    acc[h] = kv.x * q.x + kv.y * q.y + kv.z * q.z + kv.w * q.w;
                }
                #pragma unroll
                for (int off = 16; off; off >>= 1) {
                    #pragma unroll
                    for (int h = 0; h < NIH; h++)
                        acc[h] += __shfl_xor_sync(0xffffffffu, acc[h], off);
                }
                if (lane == 0) {
                    float s = 0.f;
                    #pragma unroll
                    for (int h = 0; h < NIH; h++) s += s_hw[h] * fmaxf(acc[h], 0.f);
                    g_isc[b][n] = s * IDX_SCALE;
                }
            }
            donec(C_ISC + b);
        } else if (u < U_ATTN) {
            // ===== topk: radix threshold select =====
            int b = u - U_TOPK;
            waitc(C_ISC + b, 32);
            unsigned* s_key  = (unsigned*)sm_raw;
            unsigned* s_hist = (unsigned*)(sm_raw + 16384);
            unsigned* s_scan = (unsigned*)(sm_raw + 17408);
            unsigned* s_bm   = (unsigned*)(sm_raw + 18432);
            unsigned* s_cnt  = (unsigned*)(sm_raw + 18944);
            unsigned* s_pref = (unsigned*)(sm_raw + 18948);
            int*      s_rem  = (int*)(sm_raw + 18952);
            int*      s_Bw   = (int*)(sm_raw + 18956);
            int*      s_need = (int*)(sm_raw + 18960);
            int act = act_seqs[b];
            for (int i = tid; i < MAXKV; i += 256) {
                float v = (i < act) ? g_isc[b][i] : -1e9f;
                unsigned uu = __float_as_uint(v);
                uu = (uu & 0x80000000u) ? ~uu : (uu | 0x80000000u);
                s_key[i] = uu;
            }
            if (tid == 0) { *s_cnt = 0; *s_rem = TOPK; *s_pref = 0; }
            __syncthreads();
            for (int level = 0; level < 4; level++) {
                int shift = 24 - level * 8;
                s_hist[tid] = 0;
                __syncthreads();
                unsigned pref = *s_pref;
                for (int i = tid; i < MAXKV; i += 256) {
                    unsigned uu = s_key[i];
                    if (level == 0 || (uu >> (shift + 8)) == pref)
                        atomicAdd(&s_hist[(uu >> shift) & 255u], 1u);
                }
                __syncthreads();
                s_scan[tid] = s_hist[tid];
                __syncthreads();
                #pragma unroll
                for (int off = 1; off < 256; off <<= 1) {
                    unsigned t = (tid + off < 256) ? s_scan[tid + off] : 0u;
                    __syncthreads();
                    s_scan[tid] += t;
                    __syncthreads();
                }
                int rem = *s_rem;
                unsigned cumGT = s_scan[tid] - s_hist[tid];
                if ((int)cumGT < rem && (int)s_scan[tid] >= rem) {
                    *s_pref = (pref << 8) | (unsigned)tid;
                    *s_rem = rem - (int)cumGT;
                }
                __syncthreads();
            }
            unsigned K = *s_pref;
            for (int i = tid; i < MAXKV; i += 256) {
                if (s_key[i] > K) {
                    unsigned pos = atomicAdd(s_cnt, 1u);
                    g_sel[b][pos] = i;
                    g_selval[b][pos] = (i < act) ? g_isc[b][i] : -1e9f;
                }
            }
            for (int w = tid; w < MAXKV / 32; w += 256) s_bm[w] = 0;
            __syncthreads();
            for (int i = tid; i < MAXKV; i += 256)
                if (s_key[i] == K) atomicOr(&s_bm[i >> 5], 1u << (i & 31));
            __syncthreads();
            if (tid == 0) {
                int need = *s_rem;
                int w = 0;
                for (; w < MAXKV / 32; w++) {
                    int pc = __popc(s_bm[w]);
                    if (pc >= need) break;
                    need -= pc;
                }
                *s_Bw = w; *s_need = need;
            }
            __syncthreads();
            int Bw = *s_Bw, need = *s_need;
            for (int i = tid; i < MAXKV; i += 256) {
                if (s_key[i] == K) {
                    int w = i >> 5, bit = i & 31;
                    bool take = (w < Bw) ||
                                (w == Bw && (int)__popc(s_bm[w] & ((1u << bit) - 1u)) < need);
                    if (take) {
                        unsigned pos = atomicAdd(s_cnt, 1u);
                        g_sel[b][pos] = i;
                        g_selval[b][pos] = (i < act) ? g_isc[b][i] : -1e9f;
                    }
                }
            }
            donec(C_TOPK + b);
        } else if (u < U_COMB) {
            // ===== attn partial (b, s) =====
            int idx0 = u - U_ATTN;
            int b = idx0 >> 4, s = idx0 & 15;
            waitc2(C_TOPK + b, 1, C_QP + (b >> 3), 32);
            float* s_qlat = (float*)sm_raw;
            float* s_qpe  = (float*)(sm_raw + 32768);
            float* s_sc   = (float*)(sm_raw + 36864);
            const float** s_ckvp = (const float**)(sm_raw + 40960);
            const float** s_krp  = (const float**)(sm_raw + 41472);
            int* s_vld = (int*)(sm_raw + 41984);
            const float* qlb = &g_qlat[b][0][0];
            for (int i = tid; i < NH * KVL; i += 256) s_qlat[i] = qlb[i];
            const float* qpb = &g_qpe[b][0][0];
            for (int i = tid; i < NH * DR; i += 256) s_qpe[i] = qpb[i];
            if (tid < SPLITROWS) {
                int j = tid;
                int n = g_sel[b][s * SPLITROWS + j];
                float v = g_selval[b][s * SPLITROWS + j];
                bool valid = v > -1e8f;
                const float* cp; const float* kp;
                if (!valid) { cp = g_ckv[b]; kp = g_kr[b]; }
                else {
                    int blk = bt[b * BPS + (n >> 7)];
                    long flat = (long)blk * BLKSZ + (n & 127);
                    if (flat == (long)cidx[b]) { cp = g_ckv[b]; kp = g_kr[b]; }
                    else { cp = kvc + flat * KVL; kp = krc + flat * DR; }
                }
                s_ckvp[j] = cp; s_krp[j] = kp; s_vld[j] = valid ? 1 : 0;
            }
            __syncthreads();
            int warp = tid >> 5, lane = tid & 31;
            for (int j = warp; j < SPLITROWS; j += 8) {
                const float* ckv = s_ckvp[j];
                const float* krp = s_krp[j];
                float acc[NH];
                #pragma unroll
                for (int h = 0; h < NH; h++) acc[h] = 0.f;
                #pragma unroll
                for (int q = 0; q < 4; q++) {
                    float4 v = *(const float4*)(ckv + 4 * (lane + 32 * q));
                    #pragma unroll
                    for (int h = 0; h < NH; h++) {
                        float4 ql = *(const float4*)&s_qlat[h * KVL + 4 * (lane + 32 * q)];
                        acc[h] += v.x * ql.x + v.y * ql.y + v.z * ql.z + v.w * ql.w;
                    }
                }
                float2 kv2 = *(const float2*)(krp + 2 * lane);
                #pragma unroll
                for (int h = 0; h < NH; h++) {
                    float2 qp = *(const float2*)&s_qpe[h * DR + 2 * lane];
                    acc[h] += kv2.x * qp.x + kv2.y * qp.y;
                }
                #pragma unroll
                for (int off = 16; off; off >>= 1) {
                    #pragma unroll
                    for (int h = 0; h < NH; h++)
                        acc[h] += __shfl_xor_sync(0xffffffffu, acc[h], off);
                }
                if (lane == 0) {
                    bool valid = s_vld[j] != 0;
                    #pragma unroll
                    for (int h = 0; h < NH; h++)
                        s_sc[j * NH + h] = valid ? acc[h] * ATT_SCALE : -1e9f;
                }
            }
            __syncthreads();
            for (int h = warp; h < NH; h += 8) {
                float v0 = s_sc[(lane +  0) * NH + h];
                float v1 = s_sc[(lane + 32) * NH + h];
                float m = fmaxf(v0, v1);
                #pragma unroll
                for (int off = 16; off; off >>= 1) m = fmaxf(m, __shfl_xor_sync(0xffffffffu, m, off));
                float e0 = __expf(v0 - m), e1 = __expf(v1 - m);
                s_sc[(lane +  0) * NH + h] = e0;
                s_sc[(lane + 32) * NH + h] = e1;
                float l = e0 + e1;
                #pragma unroll
                for (int off = 16; off; off >>= 1) l += __shfl_xor_sync(0xffffffffu, l, off);
                if (lane == 0) { g_m[b][s][h] = m; g_l[b][s][h] = l; }
            }
            __syncthreads();
            #pragma unroll
            for (int half = 0; half < 2; half++) {
                int c = half * 256 + tid;
                float acc[NH];
                #pragma unroll
                for (int h = 0; h < NH; h++) acc[h] = 0.f;
                #pragma unroll 4
                for (int j = 0; j < SPLITROWS; j++) {
                    float v = s_ckvp[j][c];
                    float4 p0 = *(const float4*)&s_sc[j * NH + 0];
                    float4 p1 = *(const float4*)&s_sc[j * NH + 4];
                    float4 p2 = *(const float4*)&s_sc[j * NH + 8];
                    float4 p3 = *(const float4*)&s_sc[j * NH + 12];
                    acc[0]  += p0.x * v; acc[1]  += p0.y * v; acc[2]  += p0.z * v; acc[3]  += p0.w * v;
                    acc[4]  += p1.x * v; acc[5]  += p1.y * v; acc[6]  += p1.z * v; acc[7]  += p1.w * v;
                    acc[8]  += p2.x * v; acc[9]  += p2.y * v; acc[10] += p2.z * v; acc[11] += p2.w * v;
                    acc[12] += p3.x * v; acc[13] += p3.y * v; acc[14] += p3.z * v; acc[15] += p3.w * v;
                }
                #pragma unroll
                for (int h = 0; h < NH; h++) g_op[b][s][h][c] = acc[h];
            }
            donec(C_ATTN + b);
        } else {
            // ===== combine + output projection (b, h) =====
            int idx0 = u - U_COMB;
            int b = idx0 >> 4, h = idx0 & 15;
            waitc(C_ATTN + b, 16);
            float* s_olat = (float*)sm_raw;
            float* s_w    = (float*)(sm_raw + 2048);
            float* s_invl = (float*)(sm_raw + 2112);
            if (tid == 0) {
                float M = -1e30f;
                for (int s = 0; s < NSPLIT; s++) M = fmaxf(M, g_m[b][s][h]);
                float L = 0.f;
                for (int s = 0; s < NSPLIT; s++) {
                    float w = __expf(g_m[b][s][h] - M);
                    s_w[s] = w;
                    L += g_l[b][s][h] * w;
                }
                *s_invl = 1.f / L;
            }
            __syncthreads();
            for (int c = tid; c < KVL; c += 256) {
                float a = 0.f;
                #pragma unroll
                for (int s = 0; s < NSPLIT; s++) a += g_op[b][s][h][c] * s_w[s];
                s_olat[c] = a * (*s_invl);
            }
            __syncthreads();
            if (tid < DN) {
                int d = tid;
                const float* wk = w_uk + ((size_t)(h * DN + d)) * KVL;
                float a = 0.f;
                #pragma unroll 8
                for (int c = 0; c < KVL; c += 4) {
                    float4 o4 = *(const float4*)&s_olat[c];
                    float4 w4 = *(const float4*)&wk[c];
                    a += o4.x * w4.x + o4.y * w4.y + o4.z * w4.z + o4.w * w4.w;
                }
                out[b * (NH * DN) + h * DN + d] = a;
            }
            __syncthreads();
        }
    }

    // ===== final ack + counter reset for next graph replay =====
    __syncthreads();
    if (tid == 0) {
        __threadfence();
        unsigned a = atomicAdd(&g_ack, 1u) + 1;
        if (a == (unsigned)nb) {
            #pragma unroll
            for (int i = 0; i < 64; i++) g_cnt[i] = 0;
            g_ack = 0;
            __threadfence();
        }
    }
}

// ---------------- launch ----------------
extern "C" void kernel_launch(void* const* d_in, const int* in_sizes, int n_in,
                              void* d_out, int out_size) {
    const float* x            = (const float*)d_in[0];
    const float* w_dq         = (const float*)d_in[1];
    const float* w_uq_qr      = (const float*)d_in[2];
    const float* w_uk         = (const float*)d_in[3];
    const float* w_dkv_kr     = (const float*)d_in[4];
    const float* gamma_cq     = (const float*)d_in[5];
    const float* gamma_ckv    = (const float*)d_in[6];
    const float* sinp         = (const float*)d_in[7];
    const float* cosp         = (const float*)d_in[8];
    const int*   cache_index  = (const int*)d_in[9];
    const float* kv_cache     = (const float*)d_in[10];
    const float* kr_cache     = (const float*)d_in[11];
    const int*   block_table  = (const int*)d_in[12];
    const int*   act_seqs     = (const int*)d_in[13];
    const float* w_idx_qb     = (const float*)d_in[14];
    const float* w_idx_k      = (const float*)d_in[15];
    const float* w_idx_proj   = (const float*)d_in[16];
    const float* in_gamma_k   = (const float*)d_in[17];
    const float* in_beta_k    = (const float*)d_in[18];
    const float* index_k_cache= (const float*)d_in[19];
    float* out = (float*)d_out;

    int sms = 148, bpm = 0;
    cudaDeviceGetAttribute(&sms, cudaDevAttrMultiProcessorCount, 0);
    cudaOccupancyMaxActiveBlocksPerMultiprocessor(&bpm, k_mega, 256, 0);
    if (bpm < 1) bpm = 1;
    int nb = bpm * sms;
    if (nb > NBMAX) nb = NBMAX;

    k_mega<<<nb, 256>>>(x, w_dq, w_uq_qr, w_uk, w_dkv_kr, gamma_cq, gamma_ckv,
                        sinp, cosp, cache_index, kv_cache, kr_cache, block_table,
                        act_seqs, w_idx_qb, w_idx_k, w_idx_proj, in_gamma_k,
                        in_beta_k, index_k_cache, out, nb);
}

// round 9
// speedup vs baseline: 1.2629x; 1.2629x over previous
#include <cuda_runtime.h>
#include <cuda_bf16.h>
#include <math.h>

#define BS 16
#define HDIM 2048
#define QL 768
#define KVL 512
#define DR 64
#define DN 128
#define NH 16
#define NIH 8
#define IDXD 128
#define BLKSZ 128
#define BPS 32
#define MAXKV 4096
#define TOPK 1024
#define NSPLIT 16
#define SPLITROWS 64

#define NZ1 32          /* stage1 K-slices of 64 */
#define NZ2 12          /* stage2 K-slices of 64 */
#define T1DIM 1472
#define T2DIM 4104

#define ATT_SCALE 0.07216878364870323f
#define IDX_SCALE 0.08838834764831845f

#define NBMAX 592
#define SMSZ 42240

// ---------------- scratch ----------------
__device__ float g_t1p[NZ1][BS][T1DIM];
__device__ float g_t2p[NZ2][BS][T2DIM];
__device__ float g_cq[BS][QL];
__device__ float g_ckv[BS][KVL];
__device__ float g_kr[BS][DR];
__device__ float g_ki[BS][IDXD];
__device__ float g_q[BS][NH * 192];
__device__ float g_qi[BS][NIH * IDXD];
__device__ float g_hw[BS][NIH];
__device__ float g_qpe[BS][NH][DR];
__device__ float g_qlat[BS][NH][KVL];
__device__ float g_isc[BS][MAXKV];
__device__ int   g_sel[BS][TOPK];
__device__ float g_selval[BS][TOPK];
__device__ float g_m[BS][NSPLIT][NH];
__device__ float g_l[BS][NSPLIT][NH];
__device__ float g_op[BS][NSPLIT][NH][KVL];

// sync state (reset in-kernel before exit)
__device__ unsigned g_barcnt[8];
__device__ unsigned g_tk[BS];      // per-batch topk-done flags
__device__ unsigned g_ack;

__device__ __forceinline__ void gsync(int id, int nb) {
    __syncthreads();
    if (threadIdx.x == 0) {
        __threadfence();
        atomicAdd(&g_barcnt[id], 1u);
        while (*(volatile unsigned*)&g_barcnt[id] < (unsigned)nb) { __nanosleep(64); }
    }
    __syncthreads();
}

__device__ __forceinline__ float blockSum256(float v, float* buf) {
    int tid = threadIdx.x;
    buf[tid] = v;
    __syncthreads();
    for (int s = 128; s > 0; s >>= 1) {
        if (tid < s) buf[tid] += buf[tid + s];
        __syncthreads();
    }
    float r = buf[0];
    __syncthreads();
    return r;
}

__global__ void __launch_bounds__(256, 4)
k_mega(const float* __restrict__ x, const float* __restrict__ w_dq,
       const float* __restrict__ w_uq_qr, const float* __restrict__ w_uk,
       const float* __restrict__ w_dkv, const float* __restrict__ gamma_cq,
       const float* __restrict__ gamma_ckv, const float* __restrict__ sinp,
       const float* __restrict__ cosp, const int* __restrict__ cidx,
       const float* __restrict__ kvc, const float* __restrict__ krc,
       const int* __restrict__ bt, const int* __restrict__ act_seqs,
       const float* __restrict__ w_idx_qb, const float* __restrict__ w_idxk,
       const float* __restrict__ w_idx_proj, const float* __restrict__ in_g,
       const float* __restrict__ in_b, const float* __restrict__ ikc,
       float* __restrict__ out, int nb)
{
    __shared__ __align__(16) char sm_raw[SMSZ];
    int tid = threadIdx.x;
    int bx = blockIdx.x;

    // ===== P0: stage1 partials, 8 batches/unit, 64-deep K slices (384 units) =====
    {
        float* s_x = (float*)sm_raw;
        for (int u = bx; u < 6 * 2 * NZ1; u += nb) {
            int cx = u % 6, bg = (u / 6) & 1, z = u / 12;
            int i0 = z * 64, b0 = bg * 8;
            for (int idx = tid; idx < 8 * 64; idx += 256) {
                int bb = idx >> 6, ii = idx & 63;
                s_x[idx] = x[(b0 + bb) * HDIM + i0 + ii];
            }
            __syncthreads();
            int col = cx * 256 + tid;
            if (col < T1DIM) {
                const float* W; int stride, c;
                if (col < QL)                 { W = w_dq;   stride = QL;       c = col; }
                else if (col < QL + KVL + DR) { W = w_dkv;  stride = KVL + DR; c = col - QL; }
                else                          { W = w_idxk; stride = IDXD;     c = col - (QL + KVL + DR); }
                const float* wp = W + (size_t)i0 * stride + c;
                float acc[8];
                #pragma unroll
                for (int b = 0; b < 8; b++) acc[b] = 0.f;
                #pragma unroll 8
                for (int i = 0; i < 64; i++) {
                    float w = wp[(size_t)i * stride];
                    #pragma unroll
                    for (int b = 0; b < 8; b++) acc[b] += s_x[b * 64 + i] * w;
                }
                #pragma unroll
                for (int b = 0; b < 8; b++) g_t1p[z][b0 + b][col] = acc[b];
            }
            __syncthreads();
        }
    }
    gsync(0, nb);

    // ===== P1: norms + rope(kr) =====
    {
        float* s_t  = (float*)sm_raw;
        float* sred = (float*)(sm_raw + T1DIM * 4 + 64);
        for (int u = bx; u < BS; u += nb) {
            int b = u;
            for (int i = tid; i < T1DIM; i += 256) {
                float a = 0.f;
                #pragma unroll
                for (int z = 0; z < NZ1; z++) a += g_t1p[z][b][i];
                s_t[i] = a;
            }
            __syncthreads();
            float ss = 0.f;
            for (int i = tid; i < QL; i += 256) ss += s_t[i] * s_t[i];
            ss = blockSum256(ss, sred);
            float r = rsqrtf(ss / (float)QL + 1e-6f);
            for (int i = tid; i < QL; i += 256) g_cq[b][i] = s_t[i] * r * gamma_cq[i];
            float s2 = 0.f;
            for (int i = tid; i < KVL; i += 256) { float v = s_t[QL + i]; s2 += v * v; }
            s2 = blockSum256(s2, sred);
            float r2 = rsqrtf(s2 / (float)KVL + 1e-6f);
            for (int i = tid; i < KVL; i += 256) g_ckv[b][i] = s_t[QL + i] * r2 * gamma_ckv[i];
            if (tid < DR) {
                int d = tid;
                float v = s_t[QL + KVL + d];
                float rot = (d < 32) ? -s_t[QL + KVL + d + 32] : s_t[QL + KVL + d - 32];
                g_kr[b][d] = v * cosp[b * DR + d] + rot * sinp[b * DR + d];
            }
            float sm = 0.f;
            for (int i = tid; i < IDXD; i += 256) sm += s_t[QL + KVL + DR + i];
            sm = blockSum256(sm, sred);
            float mean = sm / (float)IDXD;
            float sv = 0.f;
            for (int i = tid; i < IDXD; i += 256) { float c = s_t[QL + KVL + DR + i] - mean; sv += c * c; }
            sv = blockSum256(sv, sred);
            float rv = rsqrtf(sv / (float)IDXD + 1e-6f);
            for (int i = tid; i < IDXD; i += 256) {
                float c = s_t[QL + KVL + DR + i] - mean;
                g_ki[b][i] = c * rv * in_g[i] + in_b[i];
            }
            __syncthreads();
        }
    }
    gsync(1, nb);

    // ===== P2: stage2 partials, 8 batches/unit (408 units) =====
    {
        float* s_cq = (float*)sm_raw;
        for (int u = bx; u < 17 * 2 * NZ2; u += nb) {
            int cx = u % 17, bg = (u / 17) & 1, z = u / 34;
            int i0 = z * 64, b0 = bg * 8;
            for (int idx = tid; idx < 8 * 64; idx += 256) {
                int bb = idx >> 6, ii = idx & 63;
                s_cq[idx] = g_cq[b0 + bb][i0 + ii];
            }
            __syncthreads();
            int col = cx * 256 + tid;
            if (col < T2DIM) {
                const float* W; int stride, c;
                if (col < 3072)      { W = w_uq_qr;    stride = 3072; c = col; }
                else if (col < 4096) { W = w_idx_qb;   stride = 1024; c = col - 3072; }
                else                 { W = w_idx_proj; stride = 8;    c = col - 4096; }
                const float* wp = W + (size_t)i0 * stride + c;
                float acc[8];
                #pragma unroll
                for (int b = 0; b < 8; b++) acc[b] = 0.f;
                #pragma unroll 8
                for (int i = 0; i < 64; i++) {
                    float w = wp[(size_t)i * stride];
                    #pragma unroll
                    for (int b = 0; b < 8; b++) acc[b] += s_cq[b * 64 + i] * w;
                }
                #pragma unroll
                for (int b = 0; b < 8; b++) g_t2p[z][b0 + b][col] = acc[b];
            }
            __syncthreads();
        }
    }
    gsync(2, nb);

    // ===== P2b: reduce stage2 partials =====
    {
        int total = BS * T2DIM;
        for (int idx = bx * 256 + tid; idx < total; idx += nb * 256) {
            int b = idx / T2DIM, col = idx % T2DIM;
            float a = 0.f;
            #pragma unroll
            for (int z = 0; z < NZ2; z++) a += g_t2p[z][b][col];
            if (col < 3072)      g_q[b][col] = a;
            else if (col < 4096) g_qi[b][col - 3072] = a;
            else                 g_hw[b][col - 4096] = a;
        }
    }
    gsync(3, nb);

    // ===== P3: iscore (512) + qprep (64) — both depend only on P2b =====
    {
        for (int u = bx; u < 512 + 64; u += nb) {
            if (u < 512) {
                int chunk = u & 31, b = u >> 5;
                float* s_qi = (float*)sm_raw;
                float* s_hw = (float*)(sm_raw + 4096);
                for (int i = tid; i < NIH * IDXD; i += 256) s_qi[i] = g_qi[b][i];
                if (tid < NIH) s_hw[tid] = g_hw[b][tid];
                __syncthreads();
                int warp = tid >> 5, lane = tid & 31;
                int act = act_seqs[b];
                int ci = cidx[b];
                for (int r = warp; r < 128; r += 8) {
                    int n = chunk * 128 + r;
                    if (n >= act) { if (lane == 0) g_isc[b][n] = -1e9f; continue; }
                    int blk = bt[b * BPS + (n >> 7)];
                    long flat = (long)blk * BLKSZ + (n & 127);
                    const float* kr = (flat == (long)ci) ? g_ki[b] : ikc + flat * IDXD;
                    float4 kv = *(const float4*)(kr + lane * 4);
                    float acc[NIH];
                    #pragma unroll
                    for (int h = 0; h < NIH; h++) {
                        float4 q = *(const float4*)&s_qi[h * IDXD + lane * 4];
                        acc[h] = kv.x * q.x + kv.y * q.y + kv.z * q.z + kv.w * q.w;
                    }
                    #pragma unroll
                    for (int off = 16; off; off >>= 1) {
                        #pragma unroll
                        for (int h = 0; h < NIH; h++)
                            acc[h] += __shfl_xor_sync(0xffffffffu, acc[h], off);
                    }
                    if (lane == 0) {
                        float s = 0.f;
                        #pragma unroll
                        for (int h = 0; h < NIH; h++) s += s_hw[h] * fmaxf(acc[h], 0.f);
                        g_isc[b][n] = s * IDX_SCALE;
                    }
                }
                __syncthreads();
            } else {
                int u2 = u - 512;
                int h = u2 & 15, r = u2 >> 4;
                int cc = r & 1, bg = r >> 1;
                int b0 = bg * 8;
                float* s_qn = (float*)sm_raw;
                for (int idx = tid; idx < 1024; idx += 256) {
                    int bb = idx >> 7, d = idx & 127;
                    s_qn[idx] = g_q[b0 + bb][h * 192 + d];
                }
                if (cc == 0) {
                    for (int idx = tid; idx < 512; idx += 256) {
                        int bb = idx >> 6, d = idx & 63;
                        int b = b0 + bb;
                        float v = g_q[b][h * 192 + DN + d];
                        float rot = (d < 32) ? -g_q[b][h * 192 + DN + d + 32] : g_q[b][h * 192 + DN + d - 32];
                        g_qpe[b][h][d] = v * cosp[b * DR + d] + rot * sinp[b * DR + d];
                    }
                }
                __syncthreads();
                int c = cc * 256 + tid;
                const float* wk = w_uk + (size_t)h * DN * KVL + c;
                float acc[8];
                #pragma unroll
                for (int b = 0; b < 8; b++) acc[b] = 0.f;
                #pragma unroll 8
                for (int d = 0; d < DN; d++) {
                    float w = wk[(size_t)d * KVL];
                    #pragma unroll
                    for (int b = 0; b < 8; b++) acc[b] += s_qn[b * 128 + d] * w;
                }
                #pragma unroll
                for (int b = 0; b < 8; b++) g_qlat[b0 + b][h][c] = acc[b];
                __syncthreads();
            }
        }
    }
    gsync(4, nb);

    // ===== P4: topk (16 units, first) + attn (256 units, waits per-b on topk flag) =====
    {
        for (int u = bx; u < 16 + 256; u += nb) {
            if (u < 16) {
                // ---- top-k radix threshold select ----
                unsigned* s_key  = (unsigned*)sm_raw;
                unsigned* s_hist = (unsigned*)(sm_raw + 16384);
                unsigned* s_scan = (unsigned*)(sm_raw + 17408);
                unsigned* s_bm   = (unsigned*)(sm_raw + 18432);
                unsigned* s_cnt  = (unsigned*)(sm_raw + 18944);
                unsigned* s_pref = (unsigned*)(sm_raw + 18948);
                int*      s_rem  = (int*)(sm_raw + 18952);
                int*      s_Bw   = (int*)(sm_raw + 18956);
                int*      s_need = (int*)(sm_raw + 18960);
                int b = u;
                int act = act_seqs[b];
                for (int i = tid; i < MAXKV; i += 256) {
                    float v = (i < act) ? g_isc[b][i] : -1e9f;
                    unsigned uu = __float_as_uint(v);
                    uu = (uu & 0x80000000u) ? ~uu : (uu | 0x80000000u);
                    s_key[i] = uu;
                }
                if (tid == 0) { *s_cnt = 0; *s_rem = TOPK; *s_pref = 0; }
                __syncthreads();
                for (int level = 0; level < 4; level++) {
                    int shift = 24 - level * 8;
                    s_hist[tid] = 0;
                    __syncthreads();
                    unsigned pref = *s_pref;
                    for (int i = tid; i < MAXKV; i += 256) {
                        unsigned uu = s_key[i];
                        if (level == 0 || (uu >> (shift + 8)) == pref)
                            atomicAdd(&s_hist[(uu >> shift) & 255u], 1u);
                    }
                    __syncthreads();
                    s_scan[tid] = s_hist[tid];
                    __syncthreads();
                    #pragma unroll
                    for (int off = 1; off < 256; off <<= 1) {
                        unsigned t = (tid + off < 256) ? s_scan[tid + off] : 0u;
                        __syncthreads();
                        s_scan[tid] += t;
                        __syncthreads();
                    }
                    int rem = *s_rem;
                    unsigned cumGT = s_scan[tid] - s_hist[tid];
                    if ((int)cumGT < rem && (int)s_scan[tid] >= rem) {
                        *s_pref = (pref << 8) | (unsigned)tid;
                        *s_rem = rem - (int)cumGT;
                    }
                    __syncthreads();
                }
                unsigned K = *s_pref;
                for (int i = tid; i < MAXKV; i += 256) {
                    if (s_key[i] > K) {
                        unsigned pos = atomicAdd(s_cnt, 1u);
                        g_sel[b][pos] = i;
                        g_selval[b][pos] = (i < act) ? g_isc[b][i] : -1e9f;
                    }
                }
                for (int w = tid; w < MAXKV / 32; w += 256) s_bm[w] = 0;
                __syncthreads();
                for (int i = tid; i < MAXKV; i += 256)
                    if (s_key[i] == K) atomicOr(&s_bm[i >> 5], 1u << (i & 31));
                __syncthreads();
                if (tid == 0) {
                    int need = *s_rem;
                    int w = 0;
                    for (; w < MAXKV / 32; w++) {
                        int pc = __popc(s_bm[w]);
                        if (pc >= need) break;
                        need -= pc;
                    }
                    *s_Bw = w; *s_need = need;
                }
                __syncthreads();
                int Bw = *s_Bw, need = *s_need;
                for (int i = tid; i < MAXKV; i += 256) {
                    if (s_key[i] == K) {
                        int w = i >> 5, bit = i & 31;
                        bool take = (w < Bw) ||
                                    (w == Bw && (int)__popc(s_bm[w] & ((1u << bit) - 1u)) < need);
                        if (take) {
                            unsigned pos = atomicAdd(s_cnt, 1u);
                            g_sel[b][pos] = i;
                            g_selval[b][pos] = (i < act) ? g_isc[b][i] : -1e9f;
                        }
                    }
                }
                __syncthreads();
                if (tid == 0) { __threadfence(); atomicExch(&g_tk[b], 1u); }
            } else {
                // ---- attn partial (b, s): wait for topk(b) ----
                int idx0 = u - 16;
                int b = idx0 >> 4, s = idx0 & 15;
                if (tid == 0) {
                    volatile unsigned* f = &g_tk[b];
                    while (*f == 0u) __nanosleep(64);
                    __threadfence();
                }
                __syncthreads();
                float* s_qlat = (float*)sm_raw;
                float* s_qpe  = (float*)(sm_raw + 32768);
                float* s_sc   = (float*)(sm_raw + 36864);
                const float** s_ckvp = (const float**)(sm_raw + 40960);
                const float** s_krp  = (const float**)(sm_raw + 41472);
                int* s_vld = (int*)(sm_raw + 41984);
                const float* qlb = &g_qlat[b][0][0];
                for (int i = tid; i < NH * KVL; i += 256) s_qlat[i] = qlb[i];
                const float* qpb = &g_qpe[b][0][0];
                for (int i = tid; i < NH * DR; i += 256) s_qpe[i] = qpb[i];
                if (tid < SPLITROWS) {
                    int j = tid;
                    int n = g_sel[b][s * SPLITROWS + j];
                    float v = g_selval[b][s * SPLITROWS + j];
                    bool valid = v > -1e8f;
                    const float* cp; const float* kp;
                    if (!valid) { cp = g_ckv[b]; kp = g_kr[b]; }
                    else {
                        int blk = bt[b * BPS + (n >> 7)];
                        long flat = (long)blk * BLKSZ + (n & 127);
                        if (flat == (long)cidx[b]) { cp = g_ckv[b]; kp = g_kr[b]; }
                        else { cp = kvc + flat * KVL; kp = krc + flat * DR; }
                    }
                    s_ckvp[j] = cp; s_krp[j] = kp; s_vld[j] = valid ? 1 : 0;
                }
                __syncthreads();
                int warp = tid >> 5, lane = tid & 31;
                for (int j = warp; j < SPLITROWS; j += 8) {
                    const float* ckv = s_ckvp[j];
                    const float* krp = s_krp[j];
                    float acc[NH];
                    #pragma unroll
                    for (int h = 0; h < NH; h++) acc[h] = 0.f;
                    #pragma unroll
                    for (int q = 0; q < 4; q++) {
                        float4 v = *(const float4*)(ckv + 4 * (lane + 32 * q));
                        #pragma unroll
                        for (int h = 0; h < NH; h++) {
                            float4 ql = *(const float4*)&s_qlat[h * KVL + 4 * (lane + 32 * q)];
                            acc[h] += v.x * ql.x + v.y * ql.y + v.z * ql.z + v.w * ql.w;
                        }
                    }
                    float2 kv2 = *(const float2*)(krp + 2 * lane);
                    #pragma unroll
                    for (int h = 0; h < NH; h++) {
                        float2 qp = *(const float2*)&s_qpe[h * DR + 2 * lane];
                        acc[h] += kv2.x * qp.x + kv2.y * qp.y;
                    }
                    #pragma unroll
                    for (int off = 16; off; off >>= 1) {
                        #pragma unroll
                        for (int h = 0; h < NH; h++)
                            acc[h] += __shfl_xor_sync(0xffffffffu, acc[h], off);
                    }
                    if (lane == 0) {
                        bool valid = s_vld[j] != 0;
                        #pragma unroll
                        for (int h = 0; h < NH; h++)
                            s_sc[j * NH + h] = valid ? acc[h] * ATT_SCALE : -1e9f;
                    }
                }
                __syncthreads();
                for (int h = warp; h < NH; h += 8) {
                    float v0 = s_sc[(lane +  0) * NH + h];
                    float v1 = s_sc[(lane + 32) * NH + h];
                    float m = fmaxf(v0, v1);
                    #pragma unroll
                    for (int off = 16; off; off >>= 1) m = fmaxf(m, __shfl_xor_sync(0xffffffffu, m, off));
                    float e0 = __expf(v0 - m), e1 = __expf(v1 - m);
                    s_sc[(lane +  0) * NH + h] = e0;
                    s_sc[(lane + 32) * NH + h] = e1;
                    float l = e0 + e1;
                    #pragma unroll
                    for (int off = 16; off; off >>= 1) l += __shfl_xor_sync(0xffffffffu, l, off);
                    if (lane == 0) { g_m[b][s][h] = m; g_l[b][s][h] = l; }
                }
                __syncthreads();
                #pragma unroll
                for (int half = 0; half < 2; half++) {
                    int c = half * 256 + tid;
                    float acc[NH];
                    #pragma unroll
                    for (int h = 0; h < NH; h++) acc[h] = 0.f;
                    #pragma unroll 4
                    for (int j = 0; j < SPLITROWS; j++) {
                        float v = s_ckvp[j][c];
                        float4 p0 = *(const float4*)&s_sc[j * NH + 0];
                        float4 p1 = *(const float4*)&s_sc[j * NH + 4];
                        float4 p2 = *(const float4*)&s_sc[j * NH + 8];
                        float4 p3 = *(const float4*)&s_sc[j * NH + 12];
                        acc[0]  += p0.x * v; acc[1]  += p0.y * v; acc[2]  += p0.z * v; acc[3]  += p0.w * v;
                        acc[4]  += p1.x * v; acc[5]  += p1.y * v; acc[6]  += p1.z * v; acc[7]  += p1.w * v;
                        acc[8]  += p2.x * v; acc[9]  += p2.y * v; acc[10] += p2.z * v; acc[11] += p2.w * v;
                        acc[12] += p3.x * v; acc[13] += p3.y * v; acc[14] += p3.z * v; acc[15] += p3.w * v;
                    }
                    #pragma unroll
                    for (int h = 0; h < NH; h++) g_op[b][s][h][c] = acc[h];
                }
                __syncthreads();
            }
        }
    }
    gsync(5, nb);

    // ===== P5: combine + output projection =====
    {
        float* s_olat = (float*)sm_raw;
        float* s_w    = (float*)(sm_raw + 2048);
        float* s_invl = (float*)(sm_raw + 2112);
        for (int u = bx; u < NH * BS; u += nb) {
            int h = u & 15, b = u >> 4;
            if (tid == 0) {
                float M = -1e30f;
                for (int s = 0; s < NSPLIT; s++) M = fmaxf(M, g_m[b][s][h]);
                float L = 0.f;
                for (int s = 0; s < NSPLIT; s++) {
                    float w = __expf(g_m[b][s][h] - M);
                    s_w[s] = w;
                    L += g_l[b][s][h] * w;
                }
                *s_invl = 1.f / L;
            }
            __syncthreads();
            for (int c = tid; c < KVL; c += 256) {
                float a = 0.f;
                #pragma unroll
                for (int s = 0; s < NSPLIT; s++) a += g_op[b][s][h][c] * s_w[s];
                s_olat[c] = a * (*s_invl);
            }
            __syncthreads();
            if (tid < DN) {
                int d = tid;
                const float* wk = w_uk + ((size_t)(h * DN + d)) * KVL;
                float a = 0.f;
                #pragma unroll 8
                for (int c = 0; c < KVL; c += 4) {
                    float4 o4 = *(const float4*)&s_olat[c];
                    float4 w4 = *(const float4*)&wk[c];
                    a += o4.x * w4.x + o4.y * w4.y + o4.z * w4.z + o4.w * w4.w;
                }
                out[b * (NH * DN) + h * DN + d] = a;
            }
            __syncthreads();
        }
    }

    // reset sync state for next graph replay
    __syncthreads();
    if (tid == 0) {
        __threadfence();
        unsigned a = atomicAdd(&g_ack, 1u) + 1;
        if (a == (unsigned)nb) {
            #pragma unroll
            for (int i = 0; i < 8; i++) g_barcnt[i] = 0;
            #pragma unroll
            for (int i = 0; i < BS; i++) g_tk[i] = 0;
            g_ack = 0;
            __threadfence();
        }
    }
}

// ---------------- launch ----------------
extern "C" void kernel_launch(void* const* d_in, const int* in_sizes, int n_in,
                              void* d_out, int out_size) {
    const float* x            = (const float*)d_in[0];
    const float* w_dq         = (const float*)d_in[1];
    const float* w_uq_qr      = (const float*)d_in[2];
    const float* w_uk         = (const float*)d_in[3];
    const float* w_dkv_kr     = (const float*)d_in[4];
    const float* gamma_cq     = (const float*)d_in[5];
    const float* gamma_ckv    = (const float*)d_in[6];
    const float* sinp         = (const float*)d_in[7];
    const float* cosp         = (const float*)d_in[8];
    const int*   cache_index  = (const int*)d_in[9];
    const float* kv_cache     = (const float*)d_in[10];
    const float* kr_cache     = (const float*)d_in[11];
    const int*   block_table  = (const int*)d_in[12];
    const int*   act_seqs     = (const int*)d_in[13];
    const float* w_idx_qb     = (const float*)d_in[14];
    const float* w_idx_k      = (const float*)d_in[15];
    const float* w_idx_proj   = (const float*)d_in[16];
    const float* in_gamma_k   = (const float*)d_in[17];
    const float* in_beta_k    = (const float*)d_in[18];
    const float* index_k_cache= (const float*)d_in[19];
    float* out = (float*)d_out;

    int sms = 148, bpm = 0;
    cudaDeviceGetAttribute(&sms, cudaDevAttrMultiProcessorCount, 0);
    cudaOccupancyMaxActiveBlocksPerMultiprocessor(&bpm, k_mega, 256, 0);
    if (bpm < 1) bpm = 1;
    int nb = bpm * sms;
    if (nb > NBMAX) nb = NBMAX;

    k_mega<<<nb, 256>>>(x, w_dq, w_uq_qr, w_uk, w_dkv_kr, gamma_cq, gamma_ckv,
                        sinp, cosp, cache_index, kv_cache, kr_cache, block_table,
                        act_seqs, w_idx_qb, w_idx_k, w_idx_proj, in_gamma_k,
                        in_beta_k, index_k_cache, out, nb);
}

// round 10
// speedup vs baseline: 1.8022x; 1.4270x over previous
#include <cuda_runtime.h>
#include <cuda_bf16.h>
#include <math.h>

#define BS 16
#define HDIM 2048
#define QL 768
#define KVL 512
#define DR 64
#define DN 128
#define NH 16
#define NIH 8
#define IDXD 128
#define BLKSZ 128
#define BPS 32
#define MAXKV 4096
#define TOPK 1024
#define NSPLIT 16
#define SPLITROWS 64

#define NZ1 32          /* stage1 K-slices of 64 */
#define NZ2 12          /* stage2 K-slices of 64 */
#define T1DIM 1472
#define T2DIM 4104

#define ATT_SCALE 0.07216878364870323f
#define IDX_SCALE 0.08838834764831845f

#define NBMAX 448
#define SMSZ 57344

// ---------------- scratch ----------------
__device__ float g_t1p[NZ1][BS][T1DIM];
__device__ float g_t2p[NZ2][BS][T2DIM];
__device__ float g_cq[BS][QL];
__device__ float g_ckv[BS][KVL];
__device__ float g_kr[BS][DR];
__device__ float g_ki[BS][IDXD];
__device__ float g_q[BS][NH * 192];
__device__ float g_qi[BS][NIH * IDXD];
__device__ float g_hw[BS][NIH];
__device__ float g_qpe[BS][NH][DR];
__device__ float g_qlat[BS][NH][KVL];
__device__ float g_isc[BS][MAXKV];
__device__ int   g_sel[BS][TOPK];
__device__ float g_selval[BS][TOPK];
__device__ float g_m[BS][NSPLIT][NH];
__device__ float g_l[BS][NSPLIT][NH];
__device__ float g_op[BS][NSPLIT][NH][KVL];

__device__ unsigned g_barcnt[8];
__device__ unsigned g_ack;

__device__ __forceinline__ void gsync(int id, int nb) {
    __syncthreads();
    if (threadIdx.x == 0) {
        __threadfence();
        atomicAdd(&g_barcnt[id], 1u);
        while (*(volatile unsigned*)&g_barcnt[id] < (unsigned)nb) { __nanosleep(64); }
    }
    __syncthreads();
}

__device__ __forceinline__ float blockSum256(float v, float* buf) {
    int tid = threadIdx.x;
    buf[tid] = v;
    __syncthreads();
    for (int s = 128; s > 0; s >>= 1) {
        if (tid < s) buf[tid] += buf[tid + s];
        __syncthreads();
    }
    float r = buf[0];
    __syncthreads();
    return r;
}

__global__ void __launch_bounds__(256, 3)
k_mega(const float* __restrict__ x, const float* __restrict__ w_dq,
       const float* __restrict__ w_uq_qr, const float* __restrict__ w_uk,
       const float* __restrict__ w_dkv, const float* __restrict__ gamma_cq,
       const float* __restrict__ gamma_ckv, const float* __restrict__ sinp,
       const float* __restrict__ cosp, const int* __restrict__ cidx,
       const float* __restrict__ kvc, const float* __restrict__ krc,
       const int* __restrict__ bt, const int* __restrict__ act_seqs,
       const float* __restrict__ w_idx_qb, const float* __restrict__ w_idxk,
       const float* __restrict__ w_idx_proj, const float* __restrict__ in_g,
       const float* __restrict__ in_b, const float* __restrict__ ikc,
       float* __restrict__ out, int nb)
{
    extern __shared__ __align__(16) char sm_raw[];
    int tid = threadIdx.x;
    int bx = blockIdx.x;

    // ===== P0: stage1 partials, 8 batches/unit, transposed smem [k][b] (384 units) =====
    {
        float* s_x = (float*)sm_raw;   // [64][8]
        for (int u = bx; u < 6 * 2 * NZ1; u += nb) {
            int cx = u % 6, bg = (u / 6) & 1, z = u / 12;
            int i0 = z * 64, b0 = bg * 8;
            for (int idx = tid; idx < 512; idx += 256) {
                int i = idx >> 3, b = idx & 7;
                s_x[idx] = x[(b0 + b) * HDIM + i0 + i];
            }
            __syncthreads();
            int col = cx * 256 + tid;
            if (col < T1DIM) {
                const float* W; int stride, c;
                if (col < QL)                 { W = w_dq;   stride = QL;       c = col; }
                else if (col < QL + KVL + DR) { W = w_dkv;  stride = KVL + DR; c = col - QL; }
                else                          { W = w_idxk; stride = IDXD;     c = col - (QL + KVL + DR); }
                const float* wp = W + (size_t)i0 * stride + c;
                float acc[8];
                #pragma unroll
                for (int b = 0; b < 8; b++) acc[b] = 0.f;
                #pragma unroll 8
                for (int i = 0; i < 64; i++) {
                    float w = wp[(size_t)i * stride];
                    float4 xa = *(const float4*)&s_x[i * 8 + 0];
                    float4 xb = *(const float4*)&s_x[i * 8 + 4];
                    acc[0] += xa.x * w; acc[1] += xa.y * w; acc[2] += xa.z * w; acc[3] += xa.w * w;
                    acc[4] += xb.x * w; acc[5] += xb.y * w; acc[6] += xb.z * w; acc[7] += xb.w * w;
                }
                #pragma unroll
                for (int b = 0; b < 8; b++) g_t1p[z][b0 + b][col] = acc[b];
            }
            __syncthreads();
        }
    }
    gsync(0, nb);

    // ===== P1: norms + rope(kr) =====
    {
        float* s_t  = (float*)sm_raw;
        float* sred = (float*)(sm_raw + T1DIM * 4 + 64);
        for (int u = bx; u < BS; u += nb) {
            int b = u;
            for (int i = tid; i < T1DIM; i += 256) {
                float a = 0.f;
                #pragma unroll
                for (int z = 0; z < NZ1; z++) a += g_t1p[z][b][i];
                s_t[i] = a;
            }
            __syncthreads();
            float ss = 0.f;
            for (int i = tid; i < QL; i += 256) ss += s_t[i] * s_t[i];
            ss = blockSum256(ss, sred);
            float r = rsqrtf(ss / (float)QL + 1e-6f);
            for (int i = tid; i < QL; i += 256) g_cq[b][i] = s_t[i] * r * gamma_cq[i];
            float s2 = 0.f;
            for (int i = tid; i < KVL; i += 256) { float v = s_t[QL + i]; s2 += v * v; }
            s2 = blockSum256(s2, sred);
            float r2 = rsqrtf(s2 / (float)KVL + 1e-6f);
            for (int i = tid; i < KVL; i += 256) g_ckv[b][i] = s_t[QL + i] * r2 * gamma_ckv[i];
            if (tid < DR) {
                int d = tid;
                float v = s_t[QL + KVL + d];
                float rot = (d < 32) ? -s_t[QL + KVL + d + 32] : s_t[QL + KVL + d - 32];
                g_kr[b][d] = v * cosp[b * DR + d] + rot * sinp[b * DR + d];
            }
            float sm = 0.f;
            for (int i = tid; i < IDXD; i += 256) sm += s_t[QL + KVL + DR + i];
            sm = blockSum256(sm, sred);
            float mean = sm / (float)IDXD;
            float sv = 0.f;
            for (int i = tid; i < IDXD; i += 256) { float c = s_t[QL + KVL + DR + i] - mean; sv += c * c; }
            sv = blockSum256(sv, sred);
            float rv = rsqrtf(sv / (float)IDXD + 1e-6f);
            for (int i = tid; i < IDXD; i += 256) {
                float c = s_t[QL + KVL + DR + i] - mean;
                g_ki[b][i] = c * rv * in_g[i] + in_b[i];
            }
            __syncthreads();
        }
    }
    gsync(1, nb);

    // ===== P2: stage2 partials, 8 batches/unit, transposed smem (408 units) =====
    {
        float* s_cq = (float*)sm_raw;   // [64][8]
        for (int u = bx; u < 17 * 2 * NZ2; u += nb) {
            int cx = u % 17, bg = (u / 17) & 1, z = u / 34;
            int i0 = z * 64, b0 = bg * 8;
            for (int idx = tid; idx < 512; idx += 256) {
                int i = idx >> 3, b = idx & 7;
                s_cq[idx] = g_cq[b0 + b][i0 + i];
            }
            __syncthreads();
            int col = cx * 256 + tid;
            if (col < T2DIM) {
                const float* W; int stride, c;
                if (col < 3072)      { W = w_uq_qr;    stride = 3072; c = col; }
                else if (col < 4096) { W = w_idx_qb;   stride = 1024; c = col - 3072; }
                else                 { W = w_idx_proj; stride = 8;    c = col - 4096; }
                const float* wp = W + (size_t)i0 * stride + c;
                float acc[8];
                #pragma unroll
                for (int b = 0; b < 8; b++) acc[b] = 0.f;
                #pragma unroll 8
                for (int i = 0; i < 64; i++) {
                    float w = wp[(size_t)i * stride];
                    float4 xa = *(const float4*)&s_cq[i * 8 + 0];
                    float4 xb = *(const float4*)&s_cq[i * 8 + 4];
                    acc[0] += xa.x * w; acc[1] += xa.y * w; acc[2] += xa.z * w; acc[3] += xa.w * w;
                    acc[4] += xb.x * w; acc[5] += xb.y * w; acc[6] += xb.z * w; acc[7] += xb.w * w;
                }
                #pragma unroll
                for (int b = 0; b < 8; b++) g_t2p[z][b0 + b][col] = acc[b];
            }
            __syncthreads();
        }
    }
    gsync(2, nb);

    // ===== P2b: reduce stage2 partials =====
    {
        int total = BS * T2DIM;
        for (int idx = bx * 256 + tid; idx < total; idx += nb * 256) {
            int b = idx / T2DIM, col = idx % T2DIM;
            float a = 0.f;
            #pragma unroll
            for (int z = 0; z < NZ2; z++) a += g_t2p[z][b][col];
            if (col < 3072)      g_q[b][col] = a;
            else if (col < 4096) g_qi[b][col - 3072] = a;
            else                 g_hw[b][col - 4096] = a;
        }
    }
    gsync(3, nb);

    // ===== P3: iscore (512 units) =====
    {
        float* s_qi = (float*)sm_raw;
        float* s_hw = (float*)(sm_raw + 4096);
        for (int u = bx; u < 512; u += nb) {
            int chunk = u & 31, b = u >> 5;
            for (int i = tid; i < NIH * IDXD; i += 256) s_qi[i] = g_qi[b][i];
            if (tid < NIH) s_hw[tid] = g_hw[b][tid];
            __syncthreads();
            int warp = tid >> 5, lane = tid & 31;
            int act = act_seqs[b];
            int ci = cidx[b];
            for (int r = warp; r < 128; r += 8) {
                int n = chunk * 128 + r;
                if (n >= act) { if (lane == 0) g_isc[b][n] = -1e9f; continue; }
                int blk = bt[b * BPS + (n >> 7)];
                long flat = (long)blk * BLKSZ + (n & 127);
                const float* kr = (flat == (long)ci) ? g_ki[b] : ikc + flat * IDXD;
                float4 kv = *(const float4*)(kr + lane * 4);
                float acc[NIH];
                #pragma unroll
                for (int h = 0; h < NIH; h++) {
                    float4 q = *(const float4*)&s_qi[h * IDXD + lane * 4];
                    acc[h] = kv.x * q.x + kv.y * q.y + kv.z * q.z + kv.w * q.w;
                }
                #pragma unroll
                for (int off = 16; off; off >>= 1) {
                    #pragma unroll
                    for (int h = 0; h < NIH; h++)
                        acc[h] += __shfl_xor_sync(0xffffffffu, acc[h], off);
                }
                if (lane == 0) {
                    float s = 0.f;
                    #pragma unroll
                    for (int h = 0; h < NIH; h++) s += s_hw[h] * fmaxf(acc[h], 0.f);
                    g_isc[b][n] = s * IDX_SCALE;
                }
            }
            __syncthreads();
        }
    }
    gsync(4, nb);

    // ===== P4: topk (16 units) + qprep (64 units) overlapped =====
    {
        for (int u = bx; u < 16 + 64; u += nb) {
            if (u < 16) {
                unsigned* s_key  = (unsigned*)sm_raw;
                unsigned* s_hist = (unsigned*)(sm_raw + 16384);
                unsigned* s_scan = (unsigned*)(sm_raw + 17408);
                unsigned* s_bm   = (unsigned*)(sm_raw + 18432);
                unsigned* s_cnt  = (unsigned*)(sm_raw + 18944);
                unsigned* s_pref = (unsigned*)(sm_raw + 18948);
                int*      s_rem  = (int*)(sm_raw + 18952);
                int*      s_Bw   = (int*)(sm_raw + 18956);
                int*      s_need = (int*)(sm_raw + 18960);
                int b = u;
                int act = act_seqs[b];
                for (int i = tid; i < MAXKV; i += 256) {
                    float v = (i < act) ? g_isc[b][i] : -1e9f;
                    unsigned uu = __float_as_uint(v);
                    uu = (uu & 0x80000000u) ? ~uu : (uu | 0x80000000u);
                    s_key[i] = uu;
                }
                if (tid == 0) { *s_cnt = 0; *s_rem = TOPK; *s_pref = 0; }
                __syncthreads();
                for (int level = 0; level < 4; level++) {
                    int shift = 24 - level * 8;
                    s_hist[tid] = 0;
                    __syncthreads();
                    unsigned pref = *s_pref;
                    for (int i = tid; i < MAXKV; i += 256) {
                        unsigned uu = s_key[i];
                        if (level == 0 || (uu >> (shift + 8)) == pref)
                            atomicAdd(&s_hist[(uu >> shift) & 255u], 1u);
                    }
                    __syncthreads();
                    s_scan[tid] = s_hist[tid];
                    __syncthreads();
                    #pragma unroll
                    for (int off = 1; off < 256; off <<= 1) {
                        unsigned t = (tid + off < 256) ? s_scan[tid + off] : 0u;
                        __syncthreads();
                        s_scan[tid] += t;
                        __syncthreads();
                    }
                    int rem = *s_rem;
                    unsigned cumGT = s_scan[tid] - s_hist[tid];
                    if ((int)cumGT < rem && (int)s_scan[tid] >= rem) {
                        *s_pref = (pref << 8) | (unsigned)tid;
                        *s_rem = rem - (int)cumGT;
                    }
                    __syncthreads();
                }
                unsigned K = *s_pref;
                for (int i = tid; i < MAXKV; i += 256) {
                    if (s_key[i] > K) {
                        unsigned pos = atomicAdd(s_cnt, 1u);
                        g_sel[b][pos] = i;
                        g_selval[b][pos] = (i < act) ? g_isc[b][i] : -1e9f;
                    }
                }
                for (int w = tid; w < MAXKV / 32; w += 256) s_bm[w] = 0;
                __syncthreads();
                for (int i = tid; i < MAXKV; i += 256)
                    if (s_key[i] == K) atomicOr(&s_bm[i >> 5], 1u << (i & 31));
                __syncthreads();
                if (tid == 0) {
                    int need = *s_rem;
                    int w = 0;
                    for (; w < MAXKV / 32; w++) {
                        int pc = __popc(s_bm[w]);
                        if (pc >= need) break;
                        need -= pc;
                    }
                    *s_Bw = w; *s_need = need;
                }
                __syncthreads();
                int Bw = *s_Bw, need = *s_need;
                for (int i = tid; i < MAXKV; i += 256) {
                    if (s_key[i] == K) {
                        int w = i >> 5, bit = i & 31;
                        bool take = (w < Bw) ||
                                    (w == Bw && (int)__popc(s_bm[w] & ((1u << bit) - 1u)) < need);
                        if (take) {
                            unsigned pos = atomicAdd(s_cnt, 1u);
                            g_sel[b][pos] = i;
                            g_selval[b][pos] = (i < act) ? g_isc[b][i] : -1e9f;
                        }
                    }
                }
                __syncthreads();
            } else {
                int u2 = u - 16;
                int h = u2 & 15, r = u2 >> 4;
                int cc = r & 1, bg = r >> 1;
                int b0 = bg * 8;
                float* s_qn = (float*)sm_raw;  // [128][8] transposed
                for (int idx = tid; idx < 1024; idx += 256) {
                    int d = idx >> 3, bb = idx & 7;
                    s_qn[idx] = g_q[b0 + bb][h * 192 + d];
                }
                if (cc == 0) {
                    for (int idx = tid; idx < 512; idx += 256) {
                        int bb = idx >> 6, d = idx & 63;
                        int b = b0 + bb;
                        float v = g_q[b][h * 192 + DN + d];
                        float rot = (d < 32) ? -g_q[b][h * 192 + DN + d + 32] : g_q[b][h * 192 + DN + d - 32];
                        g_qpe[b][h][d] = v * cosp[b * DR + d] + rot * sinp[b * DR + d];
                    }
                }
                __syncthreads();
                int c = cc * 256 + tid;
                const float* wk = w_uk + (size_t)h * DN * KVL + c;
                float acc[8];
                #pragma unroll
                for (int b = 0; b < 8; b++) acc[b] = 0.f;
                #pragma unroll 8
                for (int d = 0; d < DN; d++) {
                    float w = wk[(size_t)d * KVL];
                    float4 xa = *(const float4*)&s_qn[d * 8 + 0];
                    float4 xb = *(const float4*)&s_qn[d * 8 + 4];
                    acc[0] += xa.x * w; acc[1] += xa.y * w; acc[2] += xa.z * w; acc[3] += xa.w * w;
                    acc[4] += xb.x * w; acc[5] += xb.y * w; acc[6] += xb.z * w; acc[7] += xb.w * w;
                }
                #pragma unroll
                for (int b = 0; b < 8; b++) g_qlat[b0 + b][h][c] = acc[b];
                __syncthreads();
            }
        }
    }
    gsync(5, nb);

    // ===== P5: attention partials — online softmax, smem-staged KV (256 units) =====
    {
        float* s_qlat = (float*)sm_raw;                       // 32768 B
        float* s_qpe  = (float*)(sm_raw + 32768);             //  4096 B
        float* s_kv   = (float*)(sm_raw + 36864);             // 16384 B (8 rows x 512)
        float* s_kr   = (float*)(sm_raw + 53248);             //  2048 B (8 rows x 64)
        float* s_sc   = (float*)(sm_raw + 55296);             //   512 B (8 x 16)
        float* s_m    = (float*)(sm_raw + 55808);
        float* s_l    = (float*)(sm_raw + 55872);
        float* s_fac  = (float*)(sm_raw + 55936);
        const float** s_ckvp = (const float**)(sm_raw + 56064);
        const float** s_krp  = (const float**)(sm_raw + 56576);
        int* s_vld = (int*)(sm_raw + 57088);
        for (int u = bx; u < NSPLIT * BS; u += nb) {
            int s = u & 15, b = u >> 4;
            const float4* qlb = (const float4*)&g_qlat[b][0][0];
            for (int i = tid; i < NH * KVL / 4; i += 256) ((float4*)s_qlat)[i] = qlb[i];
            const float4* qpb = (const float4*)&g_qpe[b][0][0];
            for (int i = tid; i < NH * DR / 4; i += 256) ((float4*)s_qpe)[i] = qpb[i];
            if (tid < SPLITROWS) {
                int j = tid;
                int n = g_sel[b][s * SPLITROWS + j];
                float v = g_selval[b][s * SPLITROWS + j];
                bool valid = v > -1e8f;
                const float* cp; const float* kp;
                if (!valid) { cp = g_ckv[b]; kp = g_kr[b]; }
                else {
                    int blk = bt[b * BPS + (n >> 7)];
                    long flat = (long)blk * BLKSZ + (n & 127);
                    if (flat == (long)cidx[b]) { cp = g_ckv[b]; kp = g_kr[b]; }
                    else { cp = kvc + flat * KVL; kp = krc + flat * DR; }
                }
                s_ckvp[j] = cp; s_krp[j] = kp; s_vld[j] = valid ? 1 : 0;
            }
            if (tid < NH) { s_m[tid] = -1e30f; s_l[tid] = 0.f; }
            float o0[NH], o1[NH];
            #pragma unroll
            for (int h = 0; h < NH; h++) { o0[h] = 0.f; o1[h] = 0.f; }
            __syncthreads();
            int warp = tid >> 5, lane = tid & 31;
            for (int g = 0; g < SPLITROWS / 8; g++) {
                // stage 8 kv rows + kr rows into smem (coalesced float4)
                #pragma unroll
                for (int k = 0; k < 4; k++) {
                    int f = tid + 256 * k;
                    int r = f >> 7, pos = f & 127;
                    ((float4*)&s_kv[r * 512])[pos] = ((const float4*)s_ckvp[g * 8 + r])[pos];
                }
                if (tid < 128) {
                    int r = tid >> 4, pos = tid & 15;
                    ((float4*)&s_kr[r * 64])[pos] = ((const float4*)s_krp[g * 8 + r])[pos];
                }
                __syncthreads();
                // scores: warp w computes row w of this group
                {
                    int j = warp;
                    float acc[NH];
                    #pragma unroll
                    for (int h = 0; h < NH; h++) acc[h] = 0.f;
                    #pragma unroll
                    for (int q = 0; q < 4; q++) {
                        float4 v = *(const float4*)&s_kv[j * 512 + 4 * (lane + 32 * q)];
                        #pragma unroll
                        for (int h = 0; h < NH; h++) {
                            float4 ql = *(const float4*)&s_qlat[h * KVL + 4 * (lane + 32 * q)];
                            acc[h] += v.x * ql.x + v.y * ql.y + v.z * ql.z + v.w * ql.w;
                        }
                    }
                    float2 kv2 = *(const float2*)&s_kr[j * 64 + 2 * lane];
                    #pragma unroll
                    for (int h = 0; h < NH; h++) {
                        float2 qp = *(const float2*)&s_qpe[h * DR + 2 * lane];
                        acc[h] += kv2.x * qp.x + kv2.y * qp.y;
                    }
                    #pragma unroll
                    for (int off = 16; off; off >>= 1) {
                        #pragma unroll
                        for (int h = 0; h < NH; h++)
                            acc[h] += __shfl_xor_sync(0xffffffffu, acc[h], off);
                    }
                    if (lane == 0) {
                        bool valid = s_vld[g * 8 + j] != 0;
                        #pragma unroll
                        for (int h = 0; h < NH; h++)
                            s_sc[j * NH + h] = valid ? acc[h] * ATT_SCALE : -1e9f;
                    }
                }
                __syncthreads();
                // online m/l update: warp handles h = warp, warp+8
                #pragma unroll
                for (int hh = warp; hh < NH; hh += 8) {
                    float sc = (lane < 8) ? s_sc[lane * NH + hh] : -3.0e38f;
                    float gm = sc;
                    #pragma unroll
                    for (int off = 4; off; off >>= 1) gm = fmaxf(gm, __shfl_xor_sync(0xffffffffu, gm, off));
                    float oldm = s_m[hh];
                    float newm = fmaxf(oldm, gm);
                    float p = (lane < 8) ? __expf(sc - newm) : 0.f;
                    float sl = p;
                    #pragma unroll
                    for (int off = 4; off; off >>= 1) sl += __shfl_xor_sync(0xffffffffu, sl, off);
                    if (lane < 8) s_sc[lane * NH + hh] = p;
                    if (lane == 0) {
                        float fac = __expf(oldm - newm);
                        s_m[hh] = newm;
                        s_l[hh] = s_l[hh] * fac + sl;
                        s_fac[hh] = fac;
                    }
                }
                __syncthreads();
                // accumulate o (rescale + add), thread owns c0=tid, c1=tid+256
                {
                    float4 f0 = *(const float4*)&s_fac[0];
                    float4 f1 = *(const float4*)&s_fac[4];
                    float4 f2 = *(const float4*)&s_fac[8];
                    float4 f3 = *(const float4*)&s_fac[12];
                    o0[0]  *= f0.x; o0[1]  *= f0.y; o0[2]  *= f0.z; o0[3]  *= f0.w;
                    o0[4]  *= f1.x; o0[5]  *= f1.y; o0[6]  *= f1.z; o0[7]  *= f1.w;
                    o0[8]  *= f2.x; o0[9]  *= f2.y; o0[10] *= f2.z; o0[11] *= f2.w;
                    o0[12] *= f3.x; o0[13] *= f3.y; o0[14] *= f3.z; o0[15] *= f3.w;
                    o1[0]  *= f0.x; o1[1]  *= f0.y; o1[2]  *= f0.z; o1[3]  *= f0.w;
                    o1[4]  *= f1.x; o1[5]  *= f1.y; o1[6]  *= f1.z; o1[7]  *= f1.w;
                    o1[8]  *= f2.x; o1[9]  *= f2.y; o1[10] *= f2.z; o1[11] *= f2.w;
                    o1[12] *= f3.x; o1[13] *= f3.y; o1[14] *= f3.z; o1[15] *= f3.w;
                    int c0 = tid, c1 = tid + 256;
                    #pragma unroll
                    for (int j = 0; j < 8; j++) {
                        float va = s_kv[j * 512 + c0];
                        float vb = s_kv[j * 512 + c1];
                        float4 p0 = *(const float4*)&s_sc[j * NH + 0];
                        float4 p1 = *(const float4*)&s_sc[j * NH + 4];
                        float4 p2 = *(const float4*)&s_sc[j * NH + 8];
                        float4 p3 = *(const float4*)&s_sc[j * NH + 12];
                        o0[0]  += p0.x * va; o0[1]  += p0.y * va; o0[2]  += p0.z * va; o0[3]  += p0.w * va;
                        o0[4]  += p1.x * va; o0[5]  += p1.y * va; o0[6]  += p1.z * va; o0[7]  += p1.w * va;
                        o0[8]  += p2.x * va; o0[9]  += p2.y * va; o0[10] += p2.z * va; o0[11] += p2.w * va;
                        o0[12] += p3.x * va; o0[13] += p3.y * va; o0[14] += p3.z * va; o0[15] += p3.w * va;
                        o1[0]  += p0.x * vb; o1[1]  += p0.y * vb; o1[2]  += p0.z * vb; o1[3]  += p0.w * vb;
                        o1[4]  += p1.x * vb; o1[5]  += p1.y * vb; o1[6]  += p1.z * vb; o1[7]  += p1.w * vb;
                        o1[8]  += p2.x * vb; o1[9]  += p2.y * vb; o1[10] += p2.z * vb; o1[11] += p2.w * vb;
                        o1[12] += p3.x * vb; o1[13] += p3.y * vb; o1[14] += p3.z * vb; o1[15] += p3.w * vb;
                    }
                }
                __syncthreads();
            }
            if (tid < NH) { g_m[b][s][tid] = s_m[tid]; g_l[b][s][tid] = s_l[tid]; }
            {
                int c0 = tid, c1 = tid + 256;
                #pragma unroll
                for (int h = 0; h < NH; h++) {
                    g_op[b][s][h][c0] = o0[h];
                    g_op[b][s][h][c1] = o1[h];
                }
            }
            __syncthreads();
        }
    }
    gsync(6, nb);

    // ===== P6: combine + output projection =====
    {
        float* s_olat = (float*)sm_raw;
        float* s_w    = (float*)(sm_raw + 2048);
        float* s_invl = (float*)(sm_raw + 2112);
        for (int u = bx; u < NH * BS; u += nb) {
            int h = u & 15, b = u >> 4;
            if (tid == 0) {
                float M = -1e30f;
                for (int s = 0; s < NSPLIT; s++) M = fmaxf(M, g_m[b][s][h]);
                float L = 0.f;
                for (int s = 0; s < NSPLIT; s++) {
                    float w = __expf(g_m[b][s][h] - M);
                    s_w[s] = w;
                    L += g_l[b][s][h] * w;
                }
                *s_invl = 1.f / L;
            }
            __syncthreads();
            for (int c = tid; c < KVL; c += 256) {
                float a = 0.f;
                #pragma unroll
                for (int s = 0; s < NSPLIT; s++) a += g_op[b][s][h][c] * s_w[s];
                s_olat[c] = a * (*s_invl);
            }
            __syncthreads();
            if (tid < DN) {
                int d = tid;
                const float* wk = w_uk + ((size_t)(h * DN + d)) * KVL;
                float a = 0.f;
                #pragma unroll 8
                for (int c = 0; c < KVL; c += 4) {
                    float4 o4 = *(const float4*)&s_olat[c];
                    float4 w4 = *(const float4*)&wk[c];
                    a += o4.x * w4.x + o4.y * w4.y + o4.z * w4.z + o4.w * w4.w;
                }
                out[b * (NH * DN) + h * DN + d] = a;
            }
            __syncthreads();
        }
    }

    // reset sync state for next graph replay
    __syncthreads();
    if (tid == 0) {
        __threadfence();
        unsigned a = atomicAdd(&g_ack, 1u) + 1;
        if (a == (unsigned)nb) {
            #pragma unroll
            for (int i = 0; i < 8; i++) g_barcnt[i] = 0;
            g_ack = 0;
            __threadfence();
        }
    }
}

// ---------------- launch ----------------
extern "C" void kernel_launch(void* const* d_in, const int* in_sizes, int n_in,
                              void* d_out, int out_size) {
    const float* x            = (const float*)d_in[0];
    const float* w_dq         = (const float*)d_in[1];
    const float* w_uq_qr      = (const float*)d_in[2];
    const float* w_uk         = (const float*)d_in[3];
    const float* w_dkv_kr     = (const float*)d_in[4];
    const float* gamma_cq     = (const float*)d_in[5];
    const float* gamma_ckv    = (const float*)d_in[6];
    const float* sinp         = (const float*)d_in[7];
    const float* cosp         = (const float*)d_in[8];
    const int*   cache_index  = (const int*)d_in[9];
    const float* kv_cache     = (const float*)d_in[10];
    const float* kr_cache     = (const float*)d_in[11];
    const int*   block_table  = (const int*)d_in[12];
    const int*   act_seqs     = (const int*)d_in[13];
    const float* w_idx_qb     = (const float*)d_in[14];
    const float* w_idx_k      = (const float*)d_in[15];
    const float* w_idx_proj   = (const float*)d_in[16];
    const float* in_gamma_k   = (const float*)d_in[17];
    const float* in_beta_k    = (const float*)d_in[18];
    const float* index_k_cache= (const float*)d_in[19];
    float* out = (float*)d_out;

    cudaFuncSetAttribute(k_mega, cudaFuncAttributeMaxDynamicSharedMemorySize, SMSZ);

    int sms = 148, bpm = 0;
    cudaDeviceGetAttribute(&sms, cudaDevAttrMultiProcessorCount, 0);
    cudaOccupancyMaxActiveBlocksPerMultiprocessor(&bpm, k_mega, 256, SMSZ);
    if (bpm < 1) bpm = 1;
    int nb = bpm * sms;
    if (nb > NBMAX) nb = NBMAX;

    k_mega<<<nb, 256, SMSZ>>>(x, w_dq, w_uq_qr, w_uk, w_dkv_kr, gamma_cq, gamma_ckv,
                              sinp, cosp, cache_index, kv_cache, kr_cache, block_table,
                              act_seqs, w_idx_qb, w_idx_k, w_idx_proj, in_gamma_k,
                              in_beta_k, index_k_cache, out, nb);
}